// round 11
// baseline (speedup 1.0000x reference)
#include <cuda_runtime.h>

// x[128,3,16,64,64] (*) w[24,3,3,3,3] VALID -> +bias -> min over depth(14) -> softmax over 24ch
// out [128,24,62,62] fp32
//
// Rolling 3-generation accumulators over 16 input slices; f32x2 packed over
// (oc,oc+1). Plain pixel image in smem (conflict-free LDS.128/LDS.64),
// broadcast pairs via mov.b64 {u,u}. This round: depth-min moved to smem
// (once-per-slice RMW) to free 16 regs -> __launch_bounds__(192,4) for
// 4 blocks/SM (latency coverage was the R10 limiter).

#define THREADS 192
typedef unsigned long long ull;

__device__ __forceinline__ ull ffma2(ull a, ull b, ull c) {
    ull d;
    asm("fma.rn.f32x2 %0, %1, %2, %3;" : "=l"(d) : "l"(a), "l"(b), "l"(c));
    return d;
}
__device__ __forceinline__ ull min2(ull a, ull b) {
    float alo = __uint_as_float((unsigned)a), ahi = __uint_as_float((unsigned)(a >> 32));
    float blo = __uint_as_float((unsigned)b), bhi = __uint_as_float((unsigned)(b >> 32));
    float lo = fminf(alo, blo), hi = fminf(ahi, bhi);
    return ((ull)__float_as_uint(hi) << 32) | (ull)__float_as_uint(lo);
}
__device__ __forceinline__ ull dup(float v) {
    ull d;
    unsigned u = __float_as_uint(v);
    asm("mov.b64 %0, {%1, %1};" : "=l"(d) : "r"(u));   // single pack, <=2 MOVs in SASS
    return d;
}

// smem layout (floats):
//   wsm  [27 taps][6 ocg][12]        : 1944   (2 oc-pairs x 3 kw, kw-major)
//   ring 3 slots x [12 rows][68]     : 2448   (3cin x 4row, plain pixels, 4-col pad)
//   minbuf [128 px][26]              : 3328   (running min, then softmax result)
#define SM_WSM   0
#define SM_RING  1944
#define SM_MIN   4392
#define SM_TOTAL 7720   // floats = 30880 bytes

__device__ __forceinline__ void applyw(const float* __restrict__ wp, ull (&A)[8], const ull (&pp)[6]) {
    ulonglong2 v0 = *(const ulonglong2*)(wp);        // kw0: jp0, jp1
    ulonglong2 v1 = *(const ulonglong2*)(wp + 4);    // kw1
    ulonglong2 v2 = *(const ulonglong2*)(wp + 8);    // kw2
    ull w[3][2] = { { v0.x, v0.y }, { v1.x, v1.y }, { v2.x, v2.y } };
    #pragma unroll
    for (int kw = 0; kw < 3; ++kw)
        #pragma unroll
        for (int jp = 0; jp < 2; ++jp)
            #pragma unroll
            for (int px = 0; px < 4; ++px)
                A[jp * 4 + px] = ffma2(w[kw][jp], pp[px + kw], A[jp * 4 + px]);
}

// A0 <- kd=0 taps, A1 <- kd=1, A2 <- kd=2 (caller rotates roles)
template<bool K0, bool K1, bool K2>
__device__ __forceinline__ void slice_pass(const float* __restrict__ slot,
                                           const float* __restrict__ wsm,
                                           int ocg, int rwoff,
                                           ull (&A0)[8], ull (&A1)[8], ull (&A2)[8])
{
    #pragma unroll 1
    for (int ck = 0; ck < 9; ++ck) {          // ck = cin*3 + kh
        int cin = ck / 3, kh = ck % 3;
        const float* pr = slot + (cin * 4 + kh) * 68 + rwoff;   // rwoff = r*68 + w0
        float4 q  = *(const float4*)pr;        // p0..p3 (conflict-free LDS.128)
        float2 q2 = *(const float2*)(pr + 4);  // p4,p5
        ull pp[6] = { dup(q.x), dup(q.y), dup(q.z), dup(q.w), dup(q2.x), dup(q2.y) };
        const float* wb = wsm + ((cin * 9 + kh) * 6 + ocg) * 12;
        if (K0) applyw(wb,       A0, pp);
        if (K1) applyw(wb + 216, A1, pp);     // kd=1: +3 taps * 72
        if (K2) applyw(wb + 432, A2, pp);     // kd=2
    }
}

// depth-min RMW in smem (frees 16 regs vs register-resident min)
template<bool FIRST>
__device__ __forceinline__ void fold(float* __restrict__ minbuf, int pbase, int oc0,
                                     ull (&A)[8], const ull (&bini)[2]) {
    #pragma unroll
    for (int jp = 0; jp < 2; ++jp)
        #pragma unroll
        for (int px = 0; px < 4; ++px) {
            ull* q = (ull*)(minbuf + (pbase + px) * 26 + oc0 + 2 * jp);
            ull a = A[jp * 4 + px];
            if (FIRST) *q = a;
            else       *q = min2(*q, a);
            A[jp * 4 + px] = bini[jp];
        }
}

__device__ __forceinline__ void stage_ldg(const float* __restrict__ xb, int r0, int tid,
                                          int s, float (&stg)[4]) {
    #pragma unroll
    for (int k = 0; k < 4; ++k) {
        int i = tid + k * THREADS;                 // 0..767 = 3cin*4row*64w
        int cin = i >> 8, rem = i & 255;
        int row = rem >> 6, w = rem & 63;
        stg[k] = xb[((cin * 16 + s) << 12) + ((r0 + row) << 6) + w];
    }
}
__device__ __forceinline__ void stage_sts(float* __restrict__ ring, int slot, int tid,
                                          const float (&stg)[4]) {
    float* sl = ring + slot * 816;
    #pragma unroll
    for (int k = 0; k < 4; ++k) {
        int i = tid + k * THREADS;
        int cin = i >> 8, rem = i & 255;
        int row = rem >> 6, w = rem & 63;
        sl[(cin * 4 + row) * 68 + w] = stg[k];
    }
}

__global__ __launch_bounds__(THREADS, 4)
void conv3d_min_softmax_kernel(const float* __restrict__ x,
                               const float* __restrict__ wgt,
                               const float* __restrict__ bias,
                               float* __restrict__ out)
{
    extern __shared__ float smem[];
    float* wsm    = smem + SM_WSM;
    float* ring   = smem + SM_RING;
    float* minbuf = smem + SM_MIN;

    const int tid = threadIdx.x;
    const int b   = blockIdx.y;
    const int r0  = blockIdx.x * 2;     // 0..60

    // ---- stage weights: [tap][ocg][ (kw*2+jp)*2+lane ] ----
    for (int i = tid; i < 1944; i += THREADS) {
        int tap = i / 72, rem = i % 72;
        int ocg_ = rem / 12, f = rem % 12;
        int p = f >> 1, lane = f & 1;
        int kw = p >> 1, jp = p & 1;
        int oc = ocg_ * 4 + jp * 2 + lane;
        wsm[i] = wgt[oc * 81 + tap * 3 + kw];
    }
    // zero image pads (cols 64..67 of each row, all 3 slots)
    for (int i = tid; i < 144; i += THREADS) {
        int slot = i / 48, rem = i % 48;
        int row = rem >> 2, c = rem & 3;
        ring[slot * 816 + row * 68 + 64 + c] = 0.f;
    }

    const float* xb = x + (size_t)b * (3 * 16 * 4096);
    float stg[4];

    // prologue: slices 0,1 to slots 0,1; prefetch slice 2
    stage_ldg(xb, r0, tid, 0, stg); stage_sts(ring, 0, tid, stg);
    stage_ldg(xb, r0, tid, 1, stg); stage_sts(ring, 1, tid, stg);
    stage_ldg(xb, r0, tid, 2, stg);
    __syncthreads();

    const int ocg = tid >> 5;            // 0..5, warp-uniform -> weight broadcast
    const int g   = tid & 31;
    const int r   = g >> 4;              // tile row 0..1
    const int w0  = (g & 15) * 4;        // 4 pixels per thread
    const int oc0 = ocg * 4;
    const int rwoff = r * 68 + w0;
    const int pbase = r * 64 + w0;

    ull bini[2];
    #pragma unroll
    for (int jp = 0; jp < 2; ++jp)
        bini[jp] = *(const ull*)(bias + oc0 + 2 * jp);

    ull A[3][8];
    #pragma unroll
    for (int gix = 0; gix < 3; ++gix)
        #pragma unroll
        for (int t = 0; t < 8; ++t) A[gix][t] = bini[t >> 2];

    const float* slot0 = ring;
    const float* slot1 = ring + 816;
    const float* slot2 = ring + 1632;

    // s=0: kd0 -> A0
    slice_pass<true, false, false>(slot0, wsm, ocg, rwoff, A[0], A[1], A[2]);
    stage_sts(ring, 2, tid, stg); stage_ldg(xb, r0, tid, 3, stg);
    __syncthreads();

    // s=1: kd0 -> A1, kd1 -> A0
    slice_pass<true, true, false>(slot1, wsm, ocg, rwoff, A[1], A[0], A[2]);
    stage_sts(ring, 0, tid, stg); stage_ldg(xb, r0, tid, 4, stg);
    __syncthreads();

    // s=2: kd0->A2, kd1->A1, kd2->A0; fold d0 (first: plain store)
    slice_pass<true, true, true>(slot2, wsm, ocg, rwoff, A[2], A[1], A[0]);
    fold<true>(minbuf, pbase, oc0, A[0], bini);
    stage_sts(ring, 1, tid, stg); stage_ldg(xb, r0, tid, 5, stg);
    __syncthreads();

    // main: s = st, st+1, st+2 for st = 3,6,9  (slices 3..11)
    #pragma unroll 1
    for (int st = 3; st <= 9; st += 3) {
        slice_pass<true, true, true>(slot0, wsm, ocg, rwoff, A[0], A[2], A[1]);
        fold<false>(minbuf, pbase, oc0, A[1], bini);
        stage_sts(ring, 2, tid, stg); stage_ldg(xb, r0, tid, st + 3, stg);
        __syncthreads();

        slice_pass<true, true, true>(slot1, wsm, ocg, rwoff, A[1], A[0], A[2]);
        fold<false>(minbuf, pbase, oc0, A[2], bini);
        stage_sts(ring, 0, tid, stg); stage_ldg(xb, r0, tid, st + 4, stg);
        __syncthreads();

        slice_pass<true, true, true>(slot2, wsm, ocg, rwoff, A[2], A[1], A[0]);
        fold<false>(minbuf, pbase, oc0, A[0], bini);
        stage_sts(ring, 1, tid, stg); stage_ldg(xb, r0, tid, st + 5, stg);
        __syncthreads();
    }

    // s=12: kd0->A0, kd1->A2, kd2->A1, fold d10
    slice_pass<true, true, true>(slot0, wsm, ocg, rwoff, A[0], A[2], A[1]);
    fold<false>(minbuf, pbase, oc0, A[1], bini);
    stage_sts(ring, 2, tid, stg); stage_ldg(xb, r0, tid, 15, stg);
    __syncthreads();

    // s=13: kd0->A1, kd1->A0, kd2->A2, fold d11
    slice_pass<true, true, true>(slot1, wsm, ocg, rwoff, A[1], A[0], A[2]);
    fold<false>(minbuf, pbase, oc0, A[2], bini);
    stage_sts(ring, 0, tid, stg);   // slice 15 -> slot 0
    __syncthreads();

    // s=14: kd1->A1 (d13), kd2->A0 (d12), fold d12
    slice_pass<false, true, true>(slot2, wsm, ocg, rwoff, A[2], A[1], A[0]);
    fold<false>(minbuf, pbase, oc0, A[0], bini);
    __syncthreads();

    // s=15: kd2->A1 (d13), fold d13
    slice_pass<false, false, true>(slot0, wsm, ocg, rwoff, A[2], A[0], A[1]);
    fold<false>(minbuf, pbase, oc0, A[1], bini);
    __syncthreads();

    // ---- softmax over 24 channels per pixel (128 pixels) ----
    if (tid < 128) {
        float* row = minbuf + tid * 26;
        float m = -3.402823466e38f;
        #pragma unroll
        for (int oc = 0; oc < 24; ++oc) m = fmaxf(m, row[oc]);
        float ssum = 0.f;
        #pragma unroll
        for (int oc = 0; oc < 24; ++oc) {
            float e = __expf(row[oc] - m);
            row[oc] = e;
            ssum += e;
        }
        float rinv = 1.0f / ssum;
        #pragma unroll
        for (int oc = 0; oc < 24; ++oc) row[oc] *= rinv;
    }
    __syncthreads();

    // ---- coalesced store (rows r0, r0+1 always < 62) ----
    float* ob = out + (size_t)b * (24 * 62 * 62);
    for (int i = tid; i < 24 * 128; i += THREADS) {
        int oc = i >> 7, pix = i & 127;
        int row = pix >> 6, w = pix & 63;
        if (w < 62)
            ob[(oc * 62 + r0 + row) * 62 + w] = minbuf[pix * 26 + oc];
    }
}

extern "C" void kernel_launch(void* const* d_in, const int* in_sizes, int n_in,
                              void* d_out, int out_size) {
    const float* x    = (const float*)d_in[0];
    const float* wgt  = (const float*)d_in[1];
    const float* bias = (const float*)d_in[2];
    float* out = (float*)d_out;

    cudaFuncSetAttribute(conv3d_min_softmax_kernel,
                         cudaFuncAttributeMaxDynamicSharedMemorySize,
                         SM_TOTAL * (int)sizeof(float));
    dim3 grid(31, 128);   // 31 two-row tiles x 128 batches
    conv3d_min_softmax_kernel<<<grid, THREADS, SM_TOTAL * sizeof(float)>>>(x, wgt, bias, out);
}

// round 12
// speedup vs baseline: 1.0676x; 1.0676x over previous
#include <cuda_runtime.h>

// x[128,3,16,64,64] (*) w[24,3,3,3,3] VALID -> +bias -> min over depth(14) -> softmax over 24ch
// out [128,24,62,62] fp32
//
// Depth-major single-generation loop: for each output depth d, read slices
// d,d+1,d+2 from a 4-slot ring. 8 pixels/thread (two conflict-free quads)
// halves weight-LDS per FFMA2 (weights were the dominant L1 traffic).
// f32x2 packed over (oc,oc+1), pixel broadcast via mov.b64 {u,u},
// min in registers, one __syncthreads per depth. 4-row tiles, (192,3).

#define THREADS 192
typedef unsigned long long ull;

__device__ __forceinline__ ull ffma2(ull a, ull b, ull c) {
    ull d;
    asm("fma.rn.f32x2 %0, %1, %2, %3;" : "=l"(d) : "l"(a), "l"(b), "l"(c));
    return d;
}
__device__ __forceinline__ ull min2(ull a, ull b) {
    float alo = __uint_as_float((unsigned)a), ahi = __uint_as_float((unsigned)(a >> 32));
    float blo = __uint_as_float((unsigned)b), bhi = __uint_as_float((unsigned)(b >> 32));
    float lo = fminf(alo, blo), hi = fminf(ahi, bhi);
    return ((ull)__float_as_uint(hi) << 32) | (ull)__float_as_uint(lo);
}
__device__ __forceinline__ ull dup(float v) {
    ull d;
    unsigned u = __float_as_uint(v);
    asm("mov.b64 %0, {%1, %1};" : "=l"(d) : "r"(u));
    return d;
}

// smem layout (floats):
//   wsm  [27 taps][6 ocg][12]        : 1944   (2 oc-pairs x 3 kw, kw-major)
//   ring 4 slots x [18 rows][68]     : 4896   (3cin x 6row, plain pixels, 4-col pad)
//   minbuf [256 px][26]              : 6656
#define SM_WSM   0
#define SM_RING  1944
#define SM_MIN   6840
#define SM_TOTAL 13496   // floats = 53984 bytes

// one (cin,kh,kd) tap-row: 12 weight floats feed 2 halves x 4 px x 2 oc-pairs
__device__ __forceinline__ void body(const float* __restrict__ pr,
                                     const float* __restrict__ wb,
                                     ull (&A)[16])
{
    ulonglong2 v0 = *(const ulonglong2*)(wb);        // kw0: jp0, jp1
    ulonglong2 v1 = *(const ulonglong2*)(wb + 4);    // kw1
    ulonglong2 v2 = *(const ulonglong2*)(wb + 8);    // kw2
    ull w[3][2] = { { v0.x, v0.y }, { v1.x, v1.y }, { v2.x, v2.y } };

    // half A: cols w0..w0+5
    {
        float4 q  = *(const float4*)pr;
        float2 q2 = *(const float2*)(pr + 4);
        ull pp[6] = { dup(q.x), dup(q.y), dup(q.z), dup(q.w), dup(q2.x), dup(q2.y) };
        #pragma unroll
        for (int kw = 0; kw < 3; ++kw)
            #pragma unroll
            for (int jp = 0; jp < 2; ++jp)
                #pragma unroll
                for (int px = 0; px < 4; ++px)
                    A[jp * 8 + px] = ffma2(w[kw][jp], pp[px + kw], A[jp * 8 + px]);
    }
    // half B: cols w0+32..w0+37
    {
        float4 q  = *(const float4*)(pr + 32);
        float2 q2 = *(const float2*)(pr + 36);
        ull pp[6] = { dup(q.x), dup(q.y), dup(q.z), dup(q.w), dup(q2.x), dup(q2.y) };
        #pragma unroll
        for (int kw = 0; kw < 3; ++kw)
            #pragma unroll
            for (int jp = 0; jp < 2; ++jp)
                #pragma unroll
                for (int px = 0; px < 4; ++px)
                    A[jp * 8 + 4 + px] = ffma2(w[kw][jp], pp[px + kw], A[jp * 8 + 4 + px]);
    }
}

__device__ __forceinline__ void stage_ldg(const float* __restrict__ xb, int r0, int tid,
                                          int s, float (&stg)[6]) {
    #pragma unroll
    for (int k = 0; k < 6; ++k) {
        int i = tid + k * THREADS;                 // 0..1151 = 3cin*6row*64w
        int cin = i / 384, rem = i % 384;
        int row = rem >> 6, w = rem & 63;
        int gr = min(r0 + row, 63);
        stg[k] = xb[((cin * 16 + s) << 12) + (gr << 6) + w];
    }
}
__device__ __forceinline__ void stage_sts(float* __restrict__ ring, int slot, int tid,
                                          const float (&stg)[6]) {
    float* sl = ring + slot * 1224;
    #pragma unroll
    for (int k = 0; k < 6; ++k) {
        int i = tid + k * THREADS;
        int cin = i / 384, rem = i % 384;
        int row = rem >> 6, w = rem & 63;
        sl[(cin * 6 + row) * 68 + w] = stg[k];
    }
}

__global__ __launch_bounds__(THREADS, 3)
void conv3d_min_softmax_kernel(const float* __restrict__ x,
                               const float* __restrict__ wgt,
                               const float* __restrict__ bias,
                               float* __restrict__ out)
{
    extern __shared__ float smem[];
    float* wsm    = smem + SM_WSM;
    float* ring   = smem + SM_RING;
    float* minbuf = smem + SM_MIN;

    const int tid = threadIdx.x;
    const int b   = blockIdx.y;
    const int r0  = blockIdx.x * 4;     // 0..60

    // ---- stage weights: [tap][ocg][ (kw*2+jp)*2+lane ] ----
    for (int i = tid; i < 1944; i += THREADS) {
        int tap = i / 72, rem = i % 72;
        int ocg_ = rem / 12, f = rem % 12;
        int p = f >> 1, lane = f & 1;
        int kw = p >> 1, jp = p & 1;
        int oc = ocg_ * 4 + jp * 2 + lane;
        wsm[i] = wgt[oc * 81 + tap * 3 + kw];
    }
    // zero image pads (cols 64..67 of each row, all 4 slots)
    for (int i = tid; i < 288; i += THREADS) {
        int slot = i / 72, rem = i % 72;
        int row = rem >> 2, c = rem & 3;
        ring[slot * 1224 + row * 68 + 64 + c] = 0.f;
    }

    const float* xb = x + (size_t)b * (3 * 16 * 4096);
    float stg[6];

    // prologue: slices 0,1 to slots 0,1; prefetch slice 2
    stage_ldg(xb, r0, tid, 0, stg); stage_sts(ring, 0, tid, stg);
    stage_ldg(xb, r0, tid, 1, stg); stage_sts(ring, 1, tid, stg);
    stage_ldg(xb, r0, tid, 2, stg);

    const int ocg = tid >> 5;            // 0..5, warp-uniform -> weight broadcast
    const int g   = tid & 31;
    const int r   = g >> 3;              // tile row 0..3
    const int w0  = (g & 7) * 4;         // quad A at w0, quad B at w0+32
    const int oc0 = ocg * 4;

    ull bini[2];
    #pragma unroll
    for (int jp = 0; jp < 2; ++jp)
        bini[jp] = *(const ull*)(bias + oc0 + 2 * jp);

    ull A[16];
    #pragma unroll
    for (int t = 0; t < 16; ++t) A[t] = bini[t >> 3];

    const ull INF2 = 0x7F8000007F800000ULL;
    ull mn[16];
    #pragma unroll
    for (int t = 0; t < 16; ++t) mn[t] = INF2;

    #pragma unroll 1
    for (int d = 0; d < 14; ++d) {
        // slot (d+2)&3 held slice d-2 (last read at compute(d-2); the sync
        // inside iteration d-1 ordered those reads before this store)
        stage_sts(ring, (d + 2) & 3, tid, stg);
        if (d + 3 <= 15) stage_ldg(xb, r0, tid, d + 3, stg);
        __syncthreads();

        const float* s0 = ring + ((d    ) & 3) * 1224;
        const float* s1 = ring + ((d + 1) & 3) * 1224;
        const float* s2 = ring + ((d + 2) & 3) * 1224;

        #pragma unroll 1
        for (int ck = 0; ck < 9; ++ck) {           // ck = cin*3 + kh
            int cin = ck / 3, kh = ck % 3;
            int rowoff = (cin * 6 + r + kh) * 68 + w0;
            const float* wt = wsm + ((cin * 9 + kh) * 6 + ocg) * 12;   // kd=0 tap
            body(s0 + rowoff, wt,       A);        // kd=0
            body(s1 + rowoff, wt + 216, A);        // kd=1 (+3 taps * 72)
            body(s2 + rowoff, wt + 432, A);        // kd=2
        }

        #pragma unroll
        for (int t = 0; t < 16; ++t) {
            mn[t] = min2(mn[t], A[t]);
            A[t] = bini[t >> 3];
        }
    }

    // ---- write per-thread mins to smem ----
    #pragma unroll
    for (int jp = 0; jp < 2; ++jp)
        #pragma unroll
        for (int hf = 0; hf < 2; ++hf)
            #pragma unroll
            for (int px = 0; px < 4; ++px) {
                int pix = r * 64 + hf * 32 + w0 + px;
                *(ull*)(minbuf + pix * 26 + oc0 + 2 * jp) = mn[jp * 8 + hf * 4 + px];
            }
    __syncthreads();

    // ---- softmax over 24 channels per pixel (256 pixels) ----
    for (int p = tid; p < 256; p += THREADS) {
        float* row = minbuf + p * 26;
        float m = -3.402823466e38f;
        #pragma unroll
        for (int oc = 0; oc < 24; ++oc) m = fmaxf(m, row[oc]);
        float ssum = 0.f;
        #pragma unroll
        for (int oc = 0; oc < 24; ++oc) {
            float e = __expf(row[oc] - m);
            row[oc] = e;
            ssum += e;
        }
        float rinv = 1.0f / ssum;
        #pragma unroll
        for (int oc = 0; oc < 24; ++oc) row[oc] *= rinv;
    }
    __syncthreads();

    // ---- coalesced store ----
    float* ob = out + (size_t)b * (24 * 62 * 62);
    for (int i = tid; i < 24 * 256; i += THREADS) {
        int oc = i >> 8, pix = i & 255;
        int row = pix >> 6, w = pix & 63;
        int oh = r0 + row;
        if (w < 62 && oh < 62)
            ob[(oc * 62 + oh) * 62 + w] = minbuf[pix * 26 + oc];
    }
}

extern "C" void kernel_launch(void* const* d_in, const int* in_sizes, int n_in,
                              void* d_out, int out_size) {
    const float* x    = (const float*)d_in[0];
    const float* wgt  = (const float*)d_in[1];
    const float* bias = (const float*)d_in[2];
    float* out = (float*)d_out;

    cudaFuncSetAttribute(conv3d_min_softmax_kernel,
                         cudaFuncAttributeMaxDynamicSharedMemorySize,
                         SM_TOTAL * (int)sizeof(float));
    dim3 grid(16, 128);   // 16 four-row tiles x 128 batches
    conv3d_min_softmax_kernel<<<grid, THREADS, SM_TOTAL * sizeof(float)>>>(x, wgt, bias, out);
}